// round 10
// baseline (speedup 1.0000x reference)
#include <cuda_runtime.h>

// R2Ntab: out[b] = (# rules r with h[b,r] > 0.999999) * [w_or>0] + b_or,
// h[b,r] = x_b . rw_r + b_and[r] - relu(rw_r).sum(), rw = w_and masked by
// w_cancel<0 columns. x binary {0,1} => pass <=> deficit(sum |w| over
// mismatched care features) < eps_r = b_and[r]-0.999999, which when
// |w| >= eps on all care features is EXACTLY the 256-bit pattern match
// (x_bits & care_r) == pos_r. Tiny weights -> don't-care if their total
// < eps, else that rule takes an exact fp32-dot fallback (expected: none).
//
// R9: word w = features [32w, 32w+32). Fast path reads only each row's
// first 128B. Changes vs R8:
//  - default-cached loads (NOT __ldcs): the 16.8MB fast-path working set
//    fits L2 (126MB) and persists across graph replays -> steady-state
//    loads are L2 hits, bypassing the DRAM page-efficiency penalty.
//  - 8 batched independent ballots + one REDUX.OR instead of 8 serial
//    ballot pairs; one coalesced 8-lane store instead of 8 lane-0 STGs.

#define FDIM 256
#define RDIM 128
#define UNROLL 8
#define NTHREADS 256
#define NBLOCKS 592
#define FULLM 0xffffffffu

__device__ unsigned g_pos[8][RDIM];
__device__ unsigned g_care[8][RDIM];
__device__ float    g_thresh[RDIM];
__device__ float    g_rw[RDIM * FDIM];
__device__ int      g_exact_flag[RDIM];

// ---------------------------------------------------------------------------
// Prep: one warp per rule. Word w bit j <-> feature 32w + j.
// ---------------------------------------------------------------------------
__global__ void prep_kernel(const float* __restrict__ wc,
                            const float* __restrict__ wa,
                            const float* __restrict__ ba,
                            const float* __restrict__ wo) {
    int gt   = blockIdx.x * blockDim.x + threadIdx.x;
    int r    = gt >> 5;
    int lane = gt & 31;
    if (r >= RDIM) return;

    float eps     = ba[r] - 0.999999f;
    bool  include = wo[r] > 0.0f;

    float relu_sum = 0.f, sum_tiny = 0.f;
    unsigned pos[8], care[8];
#pragma unroll
    for (int w = 0; w < 8; w++) {
        int   f  = 32 * w + lane;
        float wv = (wc[f] < 0.f) ? 0.f : wa[r * FDIM + f];
        g_rw[r * FDIM + f] = wv;
        relu_sum += fmaxf(wv, 0.f);
        float aw   = fabsf(wv);
        bool  must = (aw >= eps);
        if (!must) sum_tiny += aw;
        pos[w]  = __ballot_sync(FULLM, must && (wv > 0.f));
        care[w] = __ballot_sync(FULLM, must && (wv != 0.f));
    }
#pragma unroll
    for (int o = 16; o; o >>= 1) {
        relu_sum += __shfl_xor_sync(FULLM, relu_sum, o);
        sum_tiny += __shfl_xor_sync(FULLM, sum_tiny, o);
    }

    bool afalse = (!include) || (eps <= 0.f);
    bool exact  = (!afalse) && (sum_tiny >= eps);
    if (afalse || exact) {
#pragma unroll
        for (int w = 0; w < 8; w++) { pos[w] = 0u; care[w] = 0u; }
        pos[0] = 0xFFFFFFFFu;   // (x & 0) == 0xFFFFFFFF: never matches
    }
    if (lane == 0) {
        g_thresh[r]     = relu_sum - eps;
        g_exact_flag[r] = exact ? 1 : 0;
#pragma unroll
        for (int w = 0; w < 8; w++) { g_pos[w][r] = pos[w]; g_care[w][r] = care[w]; }
    }
}

// ---------------------------------------------------------------------------
// Main: warp per row. Fast path: 1 LDG.32/lane (row's first 128B, L2-hot
// across replays), 1 ballot/row, 1 REDUX per 8 rows, 1 coalesced store.
// ---------------------------------------------------------------------------
__global__ void __launch_bounds__(NTHREADS)
main_kernel(const float* __restrict__ x,
            const float* __restrict__ bor,
            float* __restrict__ out, int B) {
    __shared__ unsigned s_pos[8][RDIM];
    __shared__ unsigned s_care[8][RDIM];
    __shared__ int s_nx;
    __shared__ int s_xr[RDIM];

    const int tid = threadIdx.x;
    if (tid == 0) s_nx = 0;
    __syncthreads();
    for (int i = tid; i < 8 * RDIM; i += NTHREADS) {
        (&s_pos[0][0])[i]  = (&g_pos[0][0])[i];
        (&s_care[0][0])[i] = (&g_care[0][0])[i];
    }
    if (tid < RDIM && g_exact_flag[tid]) {
        int i = atomicAdd(&s_nx, 1);
        s_xr[i] = tid;
    }
    __syncthreads();

    const int   lane = tid & 31;
    const int   nx   = s_nx;
    const float b0   = bor[0];

    // Word-0 masks for this lane's 4 rules, register-resident.
    unsigned p0[4], c0[4];
#pragma unroll
    for (int k = 0; k < 4; k++) {
        p0[k] = s_pos[0][lane + 32 * k];
        c0[k] = s_care[0][lane + 32 * k];
    }

    const int gw = blockIdx.x * (NTHREADS >> 5) + (tid >> 5);
    const int nw = gridDim.x * (NTHREADS >> 5);
    const int nchunks = B / UNROLL;

    // Full (rare) evaluation of one row given xw0; loads words 1..7 on demand.
    auto full_row = [&](unsigned xw0, int row) {
        unsigned xw[8];
        xw[0] = xw0;
#pragma unroll
        for (int w = 1; w < 8; w++) {
            float v = x[(size_t)row * FDIM + 32 * w + lane];
            xw[w] = __ballot_sync(FULLM, v > 0.5f);
        }
        int cnt = 0;
#pragma unroll
        for (int k = 0; k < 4; k++) {
            int r = lane + 32 * k;
            unsigned acc = (xw0 & c0[k]) ^ p0[k];
            if (acc == 0u) {
#pragma unroll
                for (int w = 1; w < 8; w++)
                    acc |= (xw[w] & s_care[w][r]) ^ s_pos[w][r];
                if (acc == 0u) cnt++;
            }
        }
        for (int e = 0; e < nx; e++) {             // exact fp32 fallback
            int r = s_xr[e];
            float s = 0.f;
#pragma unroll
            for (int w = 0; w < 8; w++) {
                if ((xw[w] >> lane) & 1u)
                    s += g_rw[r * FDIM + 32 * w + lane];
            }
#pragma unroll
            for (int o = 16; o; o >>= 1)
                s += __shfl_xor_sync(FULLM, s, o);
            if (lane == 0 && s > g_thresh[r]) cnt++;
        }
#pragma unroll
        for (int o = 16; o; o >>= 1)
            cnt += __shfl_xor_sync(FULLM, cnt, o);
        if (lane == 0) out[row] = (float)cnt + b0;
    };

    for (int ch = gw; ch < nchunks; ch += nw) {
        int row0 = ch * UNROLL;

        // 8 independent LDG.32 (default caching: L2-resident across replays).
        float v[UNROLL];
#pragma unroll
        for (int u = 0; u < UNROLL; u++)
            v[u] = x[(size_t)(row0 + u) * FDIM + lane];

        // 8 independent ballots (pipelined, no interleaved dependencies).
        unsigned xw0[UNROLL];
#pragma unroll
        for (int u = 0; u < UNROLL; u++)
            xw0[u] = __ballot_sync(FULLM, v[u] > 0.5f);

        // Per-lane candidate byte: bit u = one of this lane's 4 rules
        // survives word-0 for row u. One REDUX.OR -> warp-wide row mask.
        unsigned candbyte = 0u;
#pragma unroll
        for (int u = 0; u < UNROLL; u++) {
            bool cand = false;
#pragma unroll
            for (int k = 0; k < 4; k++)
                cand |= (((xw0[u] & c0[k]) ^ p0[k]) == 0u);
            candbyte |= ((unsigned)cand) << u;
        }
        unsigned m = __reduce_or_sync(FULLM, candbyte);
        if (nx) m = 0xFFu;                        // exact rules: all rows full

        // Coalesced store for all rejected rows (the ~always case).
        if (lane < UNROLL && !((m >> lane) & 1u))
            out[row0 + lane] = b0;

        if (m) {                                   // warp-uniform, ~never
#pragma unroll
            for (int u = 0; u < UNROLL; u++)
                if ((m >> u) & 1u)
                    full_row(xw0[u], row0 + u);
        }
    }

    // Tail rows (B not divisible by UNROLL; not hit for B = 131072).
    for (int row = nchunks * UNROLL + gw; row < B; row += nw) {
        float v = x[(size_t)row * FDIM + lane];
        unsigned xw0 = __ballot_sync(FULLM, v > 0.5f);
        full_row(xw0, row);
    }
}

extern "C" void kernel_launch(void* const* d_in, const int* in_sizes, int n_in,
                              void* d_out, int out_size) {
    const float* x  = (const float*)d_in[0];   // [B, 256] binary
    const float* wc = (const float*)d_in[1];   // [256]
    const float* wa = (const float*)d_in[2];   // [128, 256]
    const float* ba = (const float*)d_in[3];   // [128]
    const float* wo = (const float*)d_in[4];   // [1, 128]
    const float* bo = (const float*)d_in[5];   // [1]
    float* out = (float*)d_out;

    int B = in_sizes[0] / FDIM;

    prep_kernel<<<16, 256>>>(wc, wa, ba, wo);      // 128 warps, 1 per rule
    main_kernel<<<NBLOCKS, NTHREADS>>>(x, bo, out, B);
}

// round 11
// speedup vs baseline: 1.0022x; 1.0022x over previous
#include <cuda_runtime.h>

// R2Ntab: out[b] = (# rules r with h[b,r] > 0.999999) * [w_or>0] + b_or,
// h[b,r] = x_b . rw_r + b_and[r] - relu(rw_r).sum(), rw = w_and masked by
// w_cancel<0 columns. x binary {0,1} => pass <=> deficit(sum |w| over
// mismatched care features) < eps_r = b_and[r]-0.999999, which when
// |w| >= eps on all care features is EXACTLY the 256-bit pattern match
// (x_bits & care_r) == pos_r. Tiny weights -> don't-care if their total
// < eps, else that rule takes an exact fp32-dot fallback (expected: none).
//
// R11: word w = features [32w, 32w+32); fast path reads only each row's
// first 128B (word-0 reject, survival ~3e-5/row). This round: the kernel
// was latency-exposed (DRAM 16%, issue 30%, occ 43%) -> UNROLL 16 (16
// independent LDG.32 in flight per warp) + launch_bounds(256,5) to hold
// 40 warps/SM. In-flight bytes/SM ~80KB >> latency-BW product.

#define FDIM 256
#define RDIM 128
#define UNROLL 16
#define NTHREADS 256
#define NBLOCKS 740
#define FULLM 0xffffffffu

__device__ unsigned g_pos[8][RDIM];
__device__ unsigned g_care[8][RDIM];
__device__ float    g_thresh[RDIM];
__device__ float    g_rw[RDIM * FDIM];
__device__ int      g_exact_flag[RDIM];

// ---------------------------------------------------------------------------
// Prep: one warp per rule. Word w bit j <-> feature 32w + j.
// ---------------------------------------------------------------------------
__global__ void prep_kernel(const float* __restrict__ wc,
                            const float* __restrict__ wa,
                            const float* __restrict__ ba,
                            const float* __restrict__ wo) {
    int gt   = blockIdx.x * blockDim.x + threadIdx.x;
    int r    = gt >> 5;
    int lane = gt & 31;
    if (r >= RDIM) return;

    float eps     = ba[r] - 0.999999f;
    bool  include = wo[r] > 0.0f;

    float relu_sum = 0.f, sum_tiny = 0.f;
    unsigned pos[8], care[8];
#pragma unroll
    for (int w = 0; w < 8; w++) {
        int   f  = 32 * w + lane;
        float wv = (wc[f] < 0.f) ? 0.f : wa[r * FDIM + f];
        g_rw[r * FDIM + f] = wv;
        relu_sum += fmaxf(wv, 0.f);
        float aw   = fabsf(wv);
        bool  must = (aw >= eps);
        if (!must) sum_tiny += aw;
        pos[w]  = __ballot_sync(FULLM, must && (wv > 0.f));
        care[w] = __ballot_sync(FULLM, must && (wv != 0.f));
    }
#pragma unroll
    for (int o = 16; o; o >>= 1) {
        relu_sum += __shfl_xor_sync(FULLM, relu_sum, o);
        sum_tiny += __shfl_xor_sync(FULLM, sum_tiny, o);
    }

    bool afalse = (!include) || (eps <= 0.f);
    bool exact  = (!afalse) && (sum_tiny >= eps);
    if (afalse || exact) {
#pragma unroll
        for (int w = 0; w < 8; w++) { pos[w] = 0u; care[w] = 0u; }
        pos[0] = 0xFFFFFFFFu;   // (x & 0) == 0xFFFFFFFF: never matches
    }
    if (lane == 0) {
        g_thresh[r]     = relu_sum - eps;
        g_exact_flag[r] = exact ? 1 : 0;
#pragma unroll
        for (int w = 0; w < 8; w++) { g_pos[w][r] = pos[w]; g_care[w][r] = care[w]; }
    }
}

// ---------------------------------------------------------------------------
// Main: warp per row. Fast path: 1 LDG.32/lane (row's first 128B), 1 ballot
// per row, 1 REDUX + 1 coalesced store per 16 rows. 16 loads in flight.
// ---------------------------------------------------------------------------
__global__ void __launch_bounds__(NTHREADS, 5)
main_kernel(const float* __restrict__ x,
            const float* __restrict__ bor,
            float* __restrict__ out, int B) {
    __shared__ unsigned s_pos[8][RDIM];
    __shared__ unsigned s_care[8][RDIM];
    __shared__ int s_nx;
    __shared__ int s_xr[RDIM];

    const int tid = threadIdx.x;
    if (tid == 0) s_nx = 0;
    __syncthreads();
    for (int i = tid; i < 8 * RDIM; i += NTHREADS) {
        (&s_pos[0][0])[i]  = (&g_pos[0][0])[i];
        (&s_care[0][0])[i] = (&g_care[0][0])[i];
    }
    if (tid < RDIM && g_exact_flag[tid]) {
        int i = atomicAdd(&s_nx, 1);
        s_xr[i] = tid;
    }
    __syncthreads();

    const int   lane = tid & 31;
    const int   nx   = s_nx;
    const float b0   = bor[0];

    // Word-0 masks for this lane's 4 rules, register-resident.
    unsigned p0[4], c0[4];
#pragma unroll
    for (int k = 0; k < 4; k++) {
        p0[k] = s_pos[0][lane + 32 * k];
        c0[k] = s_care[0][lane + 32 * k];
    }

    const int gw = blockIdx.x * (NTHREADS >> 5) + (tid >> 5);
    const int nw = gridDim.x * (NTHREADS >> 5);
    const int nchunks = B / UNROLL;

    // Full (rare) evaluation of one row given xw0; loads words 1..7 on demand.
    auto full_row = [&](unsigned xw0, int row) {
        unsigned xw[8];
        xw[0] = xw0;
#pragma unroll
        for (int w = 1; w < 8; w++) {
            float v = x[(size_t)row * FDIM + 32 * w + lane];
            xw[w] = __ballot_sync(FULLM, v > 0.5f);
        }
        int cnt = 0;
#pragma unroll
        for (int k = 0; k < 4; k++) {
            int r = lane + 32 * k;
            unsigned acc = (xw0 & c0[k]) ^ p0[k];
            if (acc == 0u) {
#pragma unroll
                for (int w = 1; w < 8; w++)
                    acc |= (xw[w] & s_care[w][r]) ^ s_pos[w][r];
                if (acc == 0u) cnt++;
            }
        }
        for (int e = 0; e < nx; e++) {             // exact fp32 fallback
            int r = s_xr[e];
            float s = 0.f;
#pragma unroll
            for (int w = 0; w < 8; w++) {
                if ((xw[w] >> lane) & 1u)
                    s += g_rw[r * FDIM + 32 * w + lane];
            }
#pragma unroll
            for (int o = 16; o; o >>= 1)
                s += __shfl_xor_sync(FULLM, s, o);
            if (lane == 0 && s > g_thresh[r]) cnt++;
        }
#pragma unroll
        for (int o = 16; o; o >>= 1)
            cnt += __shfl_xor_sync(FULLM, cnt, o);
        if (lane == 0) out[row] = (float)cnt + b0;
    };

    for (int ch = gw; ch < nchunks; ch += nw) {
        int row0 = ch * UNROLL;

        // 16 independent LDG.32: first 128B of each of 16 rows.
        float v[UNROLL];
#pragma unroll
        for (int u = 0; u < UNROLL; u++)
            v[u] = x[(size_t)(row0 + u) * FDIM + lane];

        // 16 independent ballots; v[u] dies into xw0[u].
        unsigned xw0[UNROLL];
#pragma unroll
        for (int u = 0; u < UNROLL; u++)
            xw0[u] = __ballot_sync(FULLM, v[u] > 0.5f);

        // Per-lane candidate mask: bit u = one of this lane's 4 rules
        // survives word-0 for row u. One REDUX.OR -> warp-wide row mask.
        unsigned candm = 0u;
#pragma unroll
        for (int u = 0; u < UNROLL; u++) {
            bool cand = false;
#pragma unroll
            for (int k = 0; k < 4; k++)
                cand |= (((xw0[u] & c0[k]) ^ p0[k]) == 0u);
            candm |= ((unsigned)cand) << u;
        }
        unsigned m = __reduce_or_sync(FULLM, candm);
        if (nx) m = (1u << UNROLL) - 1u;          // exact rules: all rows full

        // Coalesced store for all rejected rows (the ~always case).
        if (lane < UNROLL && !((m >> lane) & 1u))
            out[row0 + lane] = b0;

        if (m) {                                   // warp-uniform, ~never
#pragma unroll
            for (int u = 0; u < UNROLL; u++)
                if ((m >> u) & 1u)
                    full_row(xw0[u], row0 + u);
        }
    }

    // Tail rows (B not divisible by UNROLL; not hit for B = 131072).
    for (int row = nchunks * UNROLL + gw; row < B; row += nw) {
        float v = x[(size_t)row * FDIM + lane];
        unsigned xw0 = __ballot_sync(FULLM, v > 0.5f);
        full_row(xw0, row);
    }
}

extern "C" void kernel_launch(void* const* d_in, const int* in_sizes, int n_in,
                              void* d_out, int out_size) {
    const float* x  = (const float*)d_in[0];   // [B, 256] binary
    const float* wc = (const float*)d_in[1];   // [256]
    const float* wa = (const float*)d_in[2];   // [128, 256]
    const float* ba = (const float*)d_in[3];   // [128]
    const float* wo = (const float*)d_in[4];   // [1, 128]
    const float* bo = (const float*)d_in[5];   // [1]
    float* out = (float*)d_out;

    int B = in_sizes[0] / FDIM;

    prep_kernel<<<16, 256>>>(wc, wa, ba, wo);      // 128 warps, 1 per rule
    main_kernel<<<NBLOCKS, NTHREADS>>>(x, bo, out, B);
}

// round 12
// speedup vs baseline: 1.0243x; 1.0221x over previous
#include <cuda_runtime.h>

// R2Ntab: out[b] = (# rules r with h[b,r] > 0.999999) * [w_or>0] + b_or,
// h[b,r] = x_b . rw_r + b_and[r] - relu(rw_r).sum(), rw = w_and masked by
// w_cancel<0 columns. x binary {0,1} => pass <=> deficit(sum |w| over
// mismatched care features) < eps_r = b_and[r]-0.999999, which when
// |w| >= eps on all care features is EXACTLY the 256-bit pattern match
// (x_bits & care_r) == pos_r. Tiny weights -> don't-care if their total
// < eps, else that rule takes an exact fp32-dot fallback (expected: none).
//
// R12: word w = features [32w, 32w+32). Fast path reads ONE 128B word per
// row and rejects via that word's masks. NEW: the screening word g = warp
// id & 7 (warp-constant, uniform across warps), so concurrent fetches
// populate address bits 7-9 with all 8 values -> breaks the 1KB power-of-
// two stride's DRAM channel/bank camping that capped us at ~1.2TB/s.
// Impossible/exact rules carry pos[w]=0xFFFFFFFF for ALL w so they reject
// at any screening word.

#define FDIM 256
#define RDIM 128
#define UNROLL 16
#define NTHREADS 256
#define NBLOCKS 740
#define FULLM 0xffffffffu

__device__ unsigned g_pos[8][RDIM];
__device__ unsigned g_care[8][RDIM];
__device__ float    g_thresh[RDIM];
__device__ float    g_rw[RDIM * FDIM];
__device__ int      g_exact_flag[RDIM];

// ---------------------------------------------------------------------------
// Prep: one warp per rule. Word w bit j <-> feature 32w + j.
// ---------------------------------------------------------------------------
__global__ void prep_kernel(const float* __restrict__ wc,
                            const float* __restrict__ wa,
                            const float* __restrict__ ba,
                            const float* __restrict__ wo) {
    int gt   = blockIdx.x * blockDim.x + threadIdx.x;
    int r    = gt >> 5;
    int lane = gt & 31;
    if (r >= RDIM) return;

    float eps     = ba[r] - 0.999999f;
    bool  include = wo[r] > 0.0f;

    float relu_sum = 0.f, sum_tiny = 0.f;
    unsigned pos[8], care[8];
#pragma unroll
    for (int w = 0; w < 8; w++) {
        int   f  = 32 * w + lane;
        float wv = (wc[f] < 0.f) ? 0.f : wa[r * FDIM + f];
        g_rw[r * FDIM + f] = wv;
        relu_sum += fmaxf(wv, 0.f);
        float aw   = fabsf(wv);
        bool  must = (aw >= eps);
        if (!must) sum_tiny += aw;
        pos[w]  = __ballot_sync(FULLM, must && (wv > 0.f));
        care[w] = __ballot_sync(FULLM, must && (wv != 0.f));
    }
#pragma unroll
    for (int o = 16; o; o >>= 1) {
        relu_sum += __shfl_xor_sync(FULLM, relu_sum, o);
        sum_tiny += __shfl_xor_sync(FULLM, sum_tiny, o);
    }

    bool afalse = (!include) || (eps <= 0.f);
    bool exact  = (!afalse) && (sum_tiny >= eps);
    if (afalse || exact) {
        // Impossible at EVERY word: (x & 0) ^ 0xFFFFFFFF != 0 always,
        // so any screening word rejects these rules.
#pragma unroll
        for (int w = 0; w < 8; w++) { pos[w] = 0xFFFFFFFFu; care[w] = 0u; }
    }
    if (lane == 0) {
        g_thresh[r]     = relu_sum - eps;
        g_exact_flag[r] = exact ? 1 : 0;
#pragma unroll
        for (int w = 0; w < 8; w++) { g_pos[w][r] = pos[w]; g_care[w][r] = care[w]; }
    }
}

// ---------------------------------------------------------------------------
// Main: warp per row, screening word g = warp&7. Fast path: 1 LDG.32/lane
// (128B at row offset 128g), 1 ballot/row, 1 REDUX + 1 coalesced store per
// 16 rows. Survivors re-read the full row (rare).
// ---------------------------------------------------------------------------
__global__ void __launch_bounds__(NTHREADS, 5)
main_kernel(const float* __restrict__ x,
            const float* __restrict__ bor,
            float* __restrict__ out, int B) {
    __shared__ unsigned s_pos[8][RDIM];
    __shared__ unsigned s_care[8][RDIM];
    __shared__ int s_nx;
    __shared__ int s_xr[RDIM];

    const int tid = threadIdx.x;
    if (tid == 0) s_nx = 0;
    __syncthreads();
    for (int i = tid; i < 8 * RDIM; i += NTHREADS) {
        (&s_pos[0][0])[i]  = (&g_pos[0][0])[i];
        (&s_care[0][0])[i] = (&g_care[0][0])[i];
    }
    if (tid < RDIM && g_exact_flag[tid]) {
        int i = atomicAdd(&s_nx, 1);
        s_xr[i] = tid;
    }
    __syncthreads();

    const int   lane = tid & 31;
    const int   nx   = s_nx;
    const float b0   = bor[0];

    const int gw = blockIdx.x * (NTHREADS >> 5) + (tid >> 5);
    const int nw = gridDim.x * (NTHREADS >> 5);
    const int g  = gw & 7;                 // warp's screening word

    // Screening-word masks for this lane's 4 rules, register-resident.
    unsigned pg[4], cg[4];
#pragma unroll
    for (int k = 0; k < 4; k++) {
        pg[k] = s_pos[g][lane + 32 * k];
        cg[k] = s_care[g][lane + 32 * k];
    }

    const int nchunks = B / UNROLL;

    // Full (rare) evaluation of one row: read all 8 words, full check.
    auto full_row = [&](int row) {
        unsigned xw[8];
#pragma unroll
        for (int w = 0; w < 8; w++) {
            float v = x[(size_t)row * FDIM + 32 * w + lane];
            xw[w] = __ballot_sync(FULLM, v > 0.5f);
        }
        int cnt = 0;
#pragma unroll
        for (int k = 0; k < 4; k++) {
            int r = lane + 32 * k;
            unsigned acc = 0u;
#pragma unroll
            for (int w = 0; w < 8; w++)
                acc |= (xw[w] & s_care[w][r]) ^ s_pos[w][r];
            if (acc == 0u) cnt++;
        }
        for (int e = 0; e < nx; e++) {             // exact fp32 fallback
            int r = s_xr[e];
            float s = 0.f;
#pragma unroll
            for (int w = 0; w < 8; w++) {
                if ((xw[w] >> lane) & 1u)
                    s += g_rw[r * FDIM + 32 * w + lane];
            }
#pragma unroll
            for (int o = 16; o; o >>= 1)
                s += __shfl_xor_sync(FULLM, s, o);
            if (lane == 0 && s > g_thresh[r]) cnt++;
        }
#pragma unroll
        for (int o = 16; o; o >>= 1)
            cnt += __shfl_xor_sync(FULLM, cnt, o);
        if (lane == 0) out[row] = (float)cnt + b0;
    };

    for (int ch = gw; ch < nchunks; ch += nw) {
        int row0 = ch * UNROLL;

        // 16 independent LDG.32: 128B at offset 128*g of each of 16 rows.
        float v[UNROLL];
#pragma unroll
        for (int u = 0; u < UNROLL; u++)
            v[u] = x[(size_t)(row0 + u) * FDIM + 32 * g + lane];

        // 16 independent ballots; v[u] dies into xwg[u].
        unsigned xwg[UNROLL];
#pragma unroll
        for (int u = 0; u < UNROLL; u++)
            xwg[u] = __ballot_sync(FULLM, v[u] > 0.5f);

        // Per-lane candidate mask: bit u = one of this lane's 4 rules
        // survives the word-g screen for row u. One REDUX.OR -> row mask.
        unsigned candm = 0u;
#pragma unroll
        for (int u = 0; u < UNROLL; u++) {
            bool cand = false;
#pragma unroll
            for (int k = 0; k < 4; k++)
                cand |= (((xwg[u] & cg[k]) ^ pg[k]) == 0u);
            candm |= ((unsigned)cand) << u;
        }
        unsigned m = __reduce_or_sync(FULLM, candm);
        if (nx) m = (1u << UNROLL) - 1u;          // exact rules: all rows full

        // Coalesced store for all rejected rows (the ~always case).
        if (lane < UNROLL && !((m >> lane) & 1u))
            out[row0 + lane] = b0;

        if (m) {                                   // warp-uniform, ~never
#pragma unroll
            for (int u = 0; u < UNROLL; u++)
                if ((m >> u) & 1u)
                    full_row(row0 + u);
        }
    }

    // Tail rows (B not divisible by UNROLL; not hit for B = 131072).
    for (int row = nchunks * UNROLL + gw; row < B; row += nw)
        full_row(row);
}

extern "C" void kernel_launch(void* const* d_in, const int* in_sizes, int n_in,
                              void* d_out, int out_size) {
    const float* x  = (const float*)d_in[0];   // [B, 256] binary
    const float* wc = (const float*)d_in[1];   // [256]
    const float* wa = (const float*)d_in[2];   // [128, 256]
    const float* ba = (const float*)d_in[3];   // [128]
    const float* wo = (const float*)d_in[4];   // [1, 128]
    const float* bo = (const float*)d_in[5];   // [1]
    float* out = (float*)d_out;

    int B = in_sizes[0] / FDIM;

    prep_kernel<<<16, 256>>>(wc, wa, ba, wo);      // 128 warps, 1 per rule
    main_kernel<<<NBLOCKS, NTHREADS>>>(x, bo, out, B);
}